// round 17
// baseline (speedup 1.0000x reference)
#include <cuda_runtime.h>
#include <cuda_bf16.h>
#include <cstdint>

// Problem constants (fixed by the reference):
//   N_NODES = 100000, N_EDGES = 1600000, IN_F = 256, OUT_F = 128
// Inputs (metadata order): X_input[f32 N*256], adj_row[i32 E], adj_col[i32 E],
//                          adj_val[f32 E], W[f32 256*128], bias[f32 128]
// Output: f32 [N, 128]

#define MAX_NODES 100000
#define MAX_EDGES 1600000
#define IN_F      256
#define OUT_F     128

// -------------------- static device scratch (no allocs) --------------------
__device__ __align__(16) float g_support[(size_t)MAX_NODES * OUT_F]; // 51.2 MB
__device__ int  g_row_start[MAX_NODES];   // per-chunk exclusive offsets
__device__ int  g_row_cnt[MAX_NODES];     // row degrees
__device__ int  g_cursor[MAX_NODES];      // scatter cursors
__device__ int  g_blk_sum[128];           // chunk-base offsets (98 used)
__device__ __align__(8) int2 g_edge[MAX_EDGES];  // packed (col, val_bits)

// ---------------------------------------------------------------------------
// tf32 helpers
// ---------------------------------------------------------------------------
__device__ __forceinline__ uint32_t f2tf32(float x) {
    uint32_t r;
    asm("cvt.rna.tf32.f32 %0, %1;" : "=r"(r) : "f"(x));
    return r;
}

__device__ __forceinline__ void mma_tf32(float& d0, float& d1, float& d2, float& d3,
                                         uint32_t a0, uint32_t a1, uint32_t a2, uint32_t a3,
                                         uint32_t b0, uint32_t b1) {
    asm volatile(
        "mma.sync.aligned.m16n8k8.row.col.f32.tf32.tf32.f32 "
        "{%0,%1,%2,%3}, {%4,%5,%6,%7}, {%8,%9}, {%0,%1,%2,%3};\n"
        : "+f"(d0), "+f"(d1), "+f"(d2), "+f"(d3)
        : "r"(a0), "r"(a1), "r"(a2), "r"(a3), "r"(b0), "r"(b1));
}

// ---------------------------------------------------------------------------
// Kernel 1: tf32 tensor-core GEMM  S[M,128] = X[M,256] @ W[256,128]
// (unchanged from the proven 59.3us R13 version)
// ---------------------------------------------------------------------------
#define BM 128
#define BN 128
#define BKG 32
#define ASTR 44
#define BSTR 136

__global__ __launch_bounds__(256, 2)
void gemm_tf32_kernel(const float* __restrict__ X, const float* __restrict__ W,
                      float* __restrict__ S, int M) {
    __shared__ float As[BM][ASTR];   // 22528 B
    __shared__ float Bs[BKG][BSTR];  // 17408 B

    const int tid  = threadIdx.x;
    const int row0 = blockIdx.x * BM;
    const int warp = tid >> 5, lane = tid & 31;
    const int wm = warp & 1;          // 2 warps along M
    const int wn = warp >> 1;         // 4 warps along N
    const int g  = lane >> 2;         // 0..7
    const int tg = lane & 3;          // 0..3

    float acc[4][4][4];
#pragma unroll
    for (int a = 0; a < 4; a++)
#pragma unroll
        for (int b = 0; b < 4; b++)
#pragma unroll
            for (int c = 0; c < 4; c++) acc[a][b][c] = 0.0f;

    const int a_row = tid >> 3;
    const int a_c4  = tid & 7;
    const int b_kr  = tid >> 5;
    const int b_c4  = tid & 31;

    for (int k0 = 0; k0 < IN_F; k0 += BKG) {
#pragma unroll
        for (int i = 0; i < 4; i++) {
            int ar = a_row + i * 32;
            int gr = row0 + ar; if (gr >= M) gr = M - 1;
            float4 v = *(const float4*)(X + (size_t)gr * IN_F + k0 + a_c4 * 4);
            float4 c;
            c.x = __uint_as_float(f2tf32(v.x));
            c.y = __uint_as_float(f2tf32(v.y));
            c.z = __uint_as_float(f2tf32(v.z));
            c.w = __uint_as_float(f2tf32(v.w));
            *(float4*)&As[ar][a_c4 * 4] = c;
        }
#pragma unroll
        for (int i = 0; i < 4; i++) {
            int kr = b_kr + i * 8;
            float4 v = *(const float4*)(W + (size_t)(k0 + kr) * OUT_F + b_c4 * 4);
            float4 c;
            c.x = __uint_as_float(f2tf32(v.x));
            c.y = __uint_as_float(f2tf32(v.y));
            c.z = __uint_as_float(f2tf32(v.z));
            c.w = __uint_as_float(f2tf32(v.w));
            *(float4*)&Bs[kr][b_c4 * 4] = c;
        }
        __syncthreads();

#pragma unroll
        for (int ks = 0; ks < BKG / 8; ks++) {
            const int kb = ks * 8;
            uint32_t bf[4][2];
#pragma unroll
            for (int nt = 0; nt < 4; nt++) {
                int nb = wn * 32 + nt * 8;
                bf[nt][0] = __float_as_uint(Bs[kb + tg    ][nb + g]);
                bf[nt][1] = __float_as_uint(Bs[kb + 4 + tg][nb + g]);
            }
#pragma unroll
            for (int mt = 0; mt < 4; mt++) {
                int rb = wm * 64 + mt * 16;
                uint32_t a0 = __float_as_uint(As[rb + g    ][kb + tg]);
                uint32_t a1 = __float_as_uint(As[rb + 8 + g][kb + tg]);
                uint32_t a2 = __float_as_uint(As[rb + g    ][kb + 4 + tg]);
                uint32_t a3 = __float_as_uint(As[rb + 8 + g][kb + 4 + tg]);
#pragma unroll
                for (int nt = 0; nt < 4; nt++)
                    mma_tf32(acc[mt][nt][0], acc[mt][nt][1],
                             acc[mt][nt][2], acc[mt][nt][3],
                             a0, a1, a2, a3, bf[nt][0], bf[nt][1]);
            }
        }
        __syncthreads();
    }

#pragma unroll
    for (int mt = 0; mt < 4; mt++) {
        int r_lo = row0 + wm * 64 + mt * 16 + g;
        int r_hi = r_lo + 8;
#pragma unroll
        for (int nt = 0; nt < 4; nt++) {
            int col = wn * 32 + nt * 8 + 2 * tg;
            if (r_lo < M) {
                float2 o = make_float2(acc[mt][nt][0], acc[mt][nt][1]);
                *(float2*)(S + (size_t)r_lo * OUT_F + col) = o;
            }
            if (r_hi < M) {
                float2 o = make_float2(acc[mt][nt][2], acc[mt][nt][3]);
                *(float2*)(S + (size_t)r_hi * OUT_F + col) = o;
            }
        }
    }
}

// ---------------------------------------------------------------------------
// CSR build (runs on a side stream, overlapped with the GEMM — it depends
// only on the adjacency inputs). Within-row order nondeterminism only
// perturbs fp32 summation order (~1e-7), same property as red.global.add.
// ---------------------------------------------------------------------------
__global__ void zero_kernel(int N) {
    int i = blockIdx.x * blockDim.x + threadIdx.x;
    if (i < N) { g_row_cnt[i] = 0; g_cursor[i] = 0; }
}

__global__ void hist_kernel(const int* __restrict__ adj_row, int E) {
    int e = blockIdx.x * blockDim.x + threadIdx.x;
    if (e < E) atomicAdd(&g_row_cnt[adj_row[e]], 1);
}

// scan1: per-1024-chunk exclusive scan + chunk totals into g_blk_sum
__global__ void scan1_kernel(int N) {
    __shared__ int s[1024];
    int t = threadIdx.x;
    int i = blockIdx.x * 1024 + t;
    int v = (i < N) ? g_row_cnt[i] : 0;
    s[t] = v;
    __syncthreads();
#pragma unroll
    for (int off = 1; off < 1024; off <<= 1) {
        int x = (t >= off) ? s[t - off] : 0;
        __syncthreads();
        s[t] += x;
        __syncthreads();
    }
    if (i < N) g_row_start[i] = s[t] - v;
    if (t == 1023) g_blk_sum[blockIdx.x] = s[1023];
}

// scan2: parallel exclusive scan of <=128 chunk totals (one block).
// (Replaces the serial 98-iteration single-thread loop: dependent L2
// round-trips -> one shared-mem scan.)
__global__ void scan2_kernel(int nblk) {
    __shared__ int s[128];
    int t = threadIdx.x;
    int v = (t < nblk) ? g_blk_sum[t] : 0;
    s[t] = v;
    __syncthreads();
#pragma unroll
    for (int off = 1; off < 128; off <<= 1) {
        int x = (t >= off) ? s[t - off] : 0;
        __syncthreads();
        s[t] += x;
        __syncthreads();
    }
    if (t < nblk) g_blk_sum[t] = s[t] - v;   // exclusive chunk base
}

// scatter: one packed 8B write per edge. Chunk base folded in here
// (scan3 kernel eliminated; g_blk_sum[r>>10] is a cached broadcast load).
__global__ void scatter_kernel(const int* __restrict__ adj_row,
                               const int* __restrict__ adj_col,
                               const float* __restrict__ adj_val, int E) {
    int e = blockIdx.x * blockDim.x + threadIdx.x;
    if (e < E) {
        int r = adj_row[e];
        int base = g_row_start[r] + g_blk_sum[r >> 10];
        int pos  = base + atomicAdd(&g_cursor[r], 1);
        g_edge[pos] = make_int2(adj_col[e], __float_as_int(adj_val[e]));
    }
}

// ---------------------------------------------------------------------------
// CSR SpMM: warp per output row, lane owns one float4 of the 128-wide row.
// Row accumulated in registers, written ONCE. Gathers are L2-resident and
// perfectly coalesced. Bias folded in. Sits at the LTS roofline (~819 MB).
// ---------------------------------------------------------------------------
__global__ __launch_bounds__(256)
void spmm_csr_kernel(const float* __restrict__ S, const float* __restrict__ bias,
                     float* __restrict__ out, int N) {
    const int w    = (blockIdx.x * blockDim.x + threadIdx.x) >> 5;
    const int lane = threadIdx.x & 31;
    if (w >= N) return;

    const int start = g_row_start[w] + g_blk_sum[w >> 10];
    const int deg   = g_row_cnt[w];

    float4 acc = __ldg((const float4*)bias + lane);

    int i = 0;
    for (; i + 4 <= deg; i += 4) {
        int2 e0 = __ldg(g_edge + start + i + 0);
        int2 e1 = __ldg(g_edge + start + i + 1);
        int2 e2 = __ldg(g_edge + start + i + 2);
        int2 e3 = __ldg(g_edge + start + i + 3);
        float4 s0 = __ldg((const float4*)(S + (size_t)e0.x * OUT_F) + lane);
        float4 s1 = __ldg((const float4*)(S + (size_t)e1.x * OUT_F) + lane);
        float4 s2 = __ldg((const float4*)(S + (size_t)e2.x * OUT_F) + lane);
        float4 s3 = __ldg((const float4*)(S + (size_t)e3.x * OUT_F) + lane);
        float v0 = __int_as_float(e0.y), v1 = __int_as_float(e1.y);
        float v2 = __int_as_float(e2.y), v3 = __int_as_float(e3.y);
        acc.x = fmaf(v0, s0.x, acc.x); acc.y = fmaf(v0, s0.y, acc.y);
        acc.z = fmaf(v0, s0.z, acc.z); acc.w = fmaf(v0, s0.w, acc.w);
        acc.x = fmaf(v1, s1.x, acc.x); acc.y = fmaf(v1, s1.y, acc.y);
        acc.z = fmaf(v1, s1.z, acc.z); acc.w = fmaf(v1, s1.w, acc.w);
        acc.x = fmaf(v2, s2.x, acc.x); acc.y = fmaf(v2, s2.y, acc.y);
        acc.z = fmaf(v2, s2.z, acc.z); acc.w = fmaf(v2, s2.w, acc.w);
        acc.x = fmaf(v3, s3.x, acc.x); acc.y = fmaf(v3, s3.y, acc.y);
        acc.z = fmaf(v3, s3.z, acc.z); acc.w = fmaf(v3, s3.w, acc.w);
    }
    for (; i < deg; ++i) {
        int2 e = __ldg(g_edge + start + i);
        float v = __int_as_float(e.y);
        float4 s = __ldg((const float4*)(S + (size_t)e.x * OUT_F) + lane);
        acc.x = fmaf(v, s.x, acc.x); acc.y = fmaf(v, s.y, acc.y);
        acc.z = fmaf(v, s.z, acc.z); acc.w = fmaf(v, s.w, acc.w);
    }

    ((float4*)(out + (size_t)w * OUT_F))[lane] = acc;
}

// ---------------------------------------------------------------------------
// Launch: fork-join capture graph.
//   stream0:  gemm ───────────────┐
//   side:     zero→hist→scan1→scan2→scatter ┘→ spmm (stream0)
// CSR build depends only on adjacency inputs, GEMM only on X/W; the join
// before spmm enforces both. Stream/events created once (uncaptured first
// call); no allocs, all graph-capturable.
// ---------------------------------------------------------------------------
extern "C" void kernel_launch(void* const* d_in, const int* in_sizes, int n_in,
                              void* d_out, int out_size) {
    const float* X    = (const float*)d_in[0];
    const int*   arow = (const int*)  d_in[1];
    const int*   acol = (const int*)  d_in[2];
    const float* aval = (const float*)d_in[3];
    const float* W    = (const float*)d_in[4];
    const float* bias = (const float*)d_in[5];
    float*       out  = (float*)d_out;

    const int M = in_sizes[0] / IN_F;   // 100000
    const int E = in_sizes[1];          // 1600000

    static float* S = nullptr;
    static cudaStream_t s_side = nullptr;
    static cudaEvent_t  ev_fork = nullptr, ev_join = nullptr;
    if (S == nullptr) {
        void* p = nullptr;
        cudaGetSymbolAddress(&p, g_support);
        S = (float*)p;
        cudaStreamCreateWithFlags(&s_side, cudaStreamNonBlocking);
        cudaEventCreateWithFlags(&ev_fork, cudaEventDisableTiming);
        cudaEventCreateWithFlags(&ev_join, cudaEventDisableTiming);
    }

    // Fork side stream from the capture (main) stream.
    cudaEventRecord(ev_fork, 0);
    cudaStreamWaitEvent(s_side, ev_fork, 0);

    // Main stream: GEMM (tensor-pipe bound, DRAM 26% -> room for overlap).
    gemm_tf32_kernel<<<(M + BM - 1) / BM, 256>>>(X, W, S, M);

    // Side stream: CSR build (memory-light, independent of GEMM).
    zero_kernel<<<(M + 255) / 256, 256, 0, s_side>>>(M);
    hist_kernel<<<(E + 255) / 256, 256, 0, s_side>>>(arow, E);
    const int nblk = (M + 1023) / 1024;   // 98 <= 128
    scan1_kernel<<<nblk, 1024, 0, s_side>>>(M);
    scan2_kernel<<<1, 128, 0, s_side>>>(nblk);
    scatter_kernel<<<(E + 255) / 256, 256, 0, s_side>>>(arow, acol, aval, E);

    // Join: spmm needs both GEMM output and CSR arrays.
    cudaEventRecord(ev_join, s_side);
    cudaStreamWaitEvent(0, ev_join, 0);

    const int nblocks = (M + 7) / 8;   // 8 warps (rows) per 256-thread block
    spmm_csr_kernel<<<nblocks, 256>>>(S, bias, out, M);
}